// round 1
// baseline (speedup 1.0000x reference)
#include <cuda_runtime.h>

#define BATCH 512
#define NQ 16
#define DIM 65536

// 256 MB scratch state (sanctioned __device__ global; no runtime allocation)
__device__ float2 g_state[(size_t)BATCH * DIM];

__device__ __forceinline__ float2 cmul(float2 a, float2 b) {
    return make_float2(a.x * b.x - a.y * b.y, a.x * b.y + a.y * b.x);
}

// ---------------------------------------------------------------------------
// Phase 1: materialize state after ring-1 (analytic product state, reindexed
// through T^-1) and apply RY-layer-1 gates on s-bits {0..8, 14, 15}
// (wires 15..7 and 1, 0).  CTA covers bits {0..8,14,15}; bits 9..13 fixed.
// ---------------------------------------------------------------------------
__global__ void __launch_bounds__(128) k_phase1(const float* __restrict__ x,
                                                const float* __restrict__ params) {
    __shared__ float2 v[16][2];   // v_w[bit]: RY(theta0_w)*RX(x_w)|0>
    __shared__ float2 gc[16];     // (pc, ps) layer-1 per wire
    __shared__ float2 Psi[512];   // product over wires 8..15, indexed by s bits 0..8
    __shared__ float2 Phi[16];    // product over wires 0..7, indexed by (h, b8, b0)
    __shared__ float2 stage[2048];

    const int blk  = blockIdx.x;
    const int b    = blk >> 5;    // sample
    const int mid5 = blk & 31;    // s bits 9..13
    const int tid  = threadIdx.x;

    if (tid < 16) {
        const int w = tid;
        float sx, cx; sincosf(0.5f * x[b * NQ + w], &sx, &cx);
        float s0, c0; sincosf(0.5f * params[w], &s0, &c0);
        // v0 = (pc*cx, ps*sx), v1 = (ps*cx, -pc*sx)
        v[w][0] = make_float2(c0 * cx,  s0 * sx);
        v[w][1] = make_float2(s0 * cx, -c0 * sx);
        float s1, c1; sincosf(0.5f * params[NQ + w], &s1, &c1);
        gc[w] = make_float2(c1, s1);
    }
    __syncthreads();

    // Psi[n]: wires 8..15, u_w = bit(15-w) ^ bit(16-w) of the 9-bit index n
    #pragma unroll
    for (int k = 0; k < 4; k++) {
        const int n = tid + 128 * k;
        float2 acc = v[8][((n >> 7) ^ (n >> 8)) & 1];
        #pragma unroll
        for (int w = 9; w <= 15; w++) {
            const int p = 15 - w;
            acc = cmul(acc, v[w][((n >> p) ^ (n >> (p + 1))) & 1]);
        }
        Psi[n] = acc;
    }
    if (tid < 16) {
        const int h = tid >> 2, b8 = (tid >> 1) & 1, b0 = tid & 1;
        const int bit14 = h & 1, bit15 = h >> 1;
        const int bit9  = mid5 & 1,        bit10 = (mid5 >> 1) & 1;
        const int bit11 = (mid5 >> 2) & 1, bit12 = (mid5 >> 3) & 1;
        const int bit13 = (mid5 >> 4) & 1;
        float2 acc = v[0][bit15 ^ b0];                  // u0 = b15 ^ b0
        acc = cmul(acc, v[1][bit14 ^ bit15 ^ b0]);      // u1 = b14^b15^b0
        acc = cmul(acc, v[2][bit13 ^ bit14]);
        acc = cmul(acc, v[3][bit12 ^ bit13]);
        acc = cmul(acc, v[4][bit11 ^ bit12]);
        acc = cmul(acc, v[5][bit10 ^ bit11]);
        acc = cmul(acc, v[6][bit9  ^ bit10]);
        acc = cmul(acc, v[7][b8    ^ bit9]);
        Phi[tid] = acc;
    }
    __syncthreads();

    const int lane = tid & 31;   // s bits 0..4
    const int wz   = tid >> 5;   // s bits 14..15
    const int b0   = lane & 1;

    float re[16], im[16];
    #pragma unroll
    for (int r = 0; r < 16; r++) {   // r = s bits 5..8
        const int b8 = r >> 3;
        float2 a = cmul(Phi[wz * 4 + b8 * 2 + b0], Psi[(r << 5) | lane]);
        re[r] = a.x; im[r] = a.y;
    }

    // register gates: s bits 5..8  <-> wires 10..7
    #pragma unroll
    for (int rb = 0; rb < 4; rb++) {
        const float pc = gc[10 - rb].x, ps = gc[10 - rb].y;
        #pragma unroll
        for (int m = 0; m < 16; m++) {
            if (m & (1 << rb)) continue;
            const int m2 = m | (1 << rb);
            const float ar = re[m], ai = im[m], br = re[m2], bi = im[m2];
            re[m]  = pc * ar - ps * br;  im[m]  = pc * ai - ps * bi;
            re[m2] = ps * ar + pc * br;  im[m2] = ps * ai + pc * bi;
        }
    }

    // shuffle gates: s bits 0..4  <-> wires 15..11
    #pragma unroll
    for (int k = 0; k < 5; k++) {
        const float pc = gc[15 - k].x, ps = gc[15 - k].y;
        const float sg = ((lane >> k) & 1) ? ps : -ps;
        #pragma unroll
        for (int r = 0; r < 16; r++) {
            const float orr = __shfl_xor_sync(0xFFFFFFFFu, re[r], 1 << k);
            const float oii = __shfl_xor_sync(0xFFFFFFFFu, im[r], 1 << k);
            re[r] = pc * re[r] + sg * orr;
            im[r] = pc * im[r] + sg * oii;
        }
    }

    // stage to smem, apply cross-warp gates on s bits 14 (wire1), 15 (wire0)
    #pragma unroll
    for (int r = 0; r < 16; r++)
        stage[wz * 512 + (r << 5) + lane] = make_float2(re[r], im[r]);
    __syncthreads();

    const float pc1 = gc[1].x, ps1 = gc[1].y;   // wire 1 = bit 14
    const float pc0 = gc[0].x, ps0 = gc[0].y;   // wire 0 = bit 15
    const size_t sbase = (size_t)b * DIM + ((size_t)mid5 << 9);
    #pragma unroll
    for (int q = 0; q < 4; q++) {
        const int l = tid + 128 * q;
        float2 x0 = stage[0 * 512 + l], x1 = stage[1 * 512 + l];
        float2 x2 = stage[2 * 512 + l], x3 = stage[3 * 512 + l];
        // bit14 gate: pairs (x0,x1), (x2,x3)
        float2 y0 = make_float2(pc1 * x0.x - ps1 * x1.x, pc1 * x0.y - ps1 * x1.y);
        float2 y1 = make_float2(ps1 * x0.x + pc1 * x1.x, ps1 * x0.y + pc1 * x1.y);
        float2 y2 = make_float2(pc1 * x2.x - ps1 * x3.x, pc1 * x2.y - ps1 * x3.y);
        float2 y3 = make_float2(ps1 * x2.x + pc1 * x3.x, ps1 * x2.y + pc1 * x3.y);
        // bit15 gate: pairs (y0,y2), (y1,y3)
        float2 z0 = make_float2(pc0 * y0.x - ps0 * y2.x, pc0 * y0.y - ps0 * y2.y);
        float2 z2 = make_float2(ps0 * y0.x + pc0 * y2.x, ps0 * y0.y + pc0 * y2.y);
        float2 z1 = make_float2(pc0 * y1.x - ps0 * y3.x, pc0 * y1.y - ps0 * y3.y);
        float2 z3 = make_float2(ps0 * y1.x + pc0 * y3.x, ps0 * y1.y + pc0 * y3.y);
        g_state[sbase + (0u << 14) + l] = z0;
        g_state[sbase + (1u << 14) + l] = z1;
        g_state[sbase + (2u << 14) + l] = z2;
        g_state[sbase + (3u << 14) + l] = z3;
    }
}

// ---------------------------------------------------------------------------
// Phase 2: gates on s bits 9..13 (wires 6..2), probabilities, and the 16
// signed parity reductions (ring-2 folded into prefix sign masks).
// CTA covers contiguous s bits 0..13; bits 14..15 fixed per CTA.
// Thread t holds j = bits 9..13 in registers.
// ---------------------------------------------------------------------------
__global__ void __launch_bounds__(512) k_phase2(const float* __restrict__ params,
                                                float* __restrict__ out) {
    __shared__ float2 gc2[8];
    const int blk = blockIdx.x;
    const int b   = blk >> 2;
    const int hq  = blk & 3;       // s bits 14..15
    const int t   = threadIdx.x;   // s bits 0..8

    if (t >= 2 && t < 7) {
        float s1, c1; sincosf(0.5f * params[NQ + t], &s1, &c1);
        gc2[t] = make_float2(c1, s1);
    }
    __syncthreads();

    const float2* __restrict__ base =
        g_state + (size_t)b * DIM + ((size_t)hq << 14) + t;

    float re[32], im[32];
    #pragma unroll
    for (int j = 0; j < 32; j++) {
        float2 a = __ldg(&base[(size_t)j << 9]);
        re[j] = a.x; im[j] = a.y;
    }

    // gates: j bit k <-> s bit (9+k) <-> wire (6-k)
    #pragma unroll
    for (int k = 0; k < 5; k++) {
        const float pc = gc2[6 - k].x, ps = gc2[6 - k].y;
        #pragma unroll
        for (int m = 0; m < 32; m++) {
            if (m & (1 << k)) continue;
            const int m2 = m | (1 << k);
            const float ar = re[m], ai = im[m], br = re[m2], bi = im[m2];
            re[m]  = pc * ar - ps * br;  im[m]  = pc * ai - ps * bi;
            re[m2] = ps * ar + pc * br;  im[m2] = ps * ai + pc * bi;
        }
    }

    // probabilities (reuse re[] as p[])
    #pragma unroll
    for (int j = 0; j < 32; j++) re[j] = re[j] * re[j] + im[j] * im[j];

    // 6 distinct folds over j (sign masks are MSB-prefix masks):
    float SP = 0.f;
    #pragma unroll
    for (int j = 0; j < 32; j++) SP += re[j];
    float bb[16]; float S4 = 0.f;
    #pragma unroll
    for (int m = 0; m < 16; m++) { bb[m] = re[m] - re[m + 16]; S4 += bb[m]; }
    float cc[8]; float S3 = 0.f;
    #pragma unroll
    for (int m = 0; m < 8; m++) { cc[m] = bb[m] - bb[m + 8]; S3 += cc[m]; }
    float dd[4]; float S2 = 0.f;
    #pragma unroll
    for (int m = 0; m < 4; m++) { dd[m] = cc[m] - cc[m + 4]; S2 += dd[m]; }
    float e0 = dd[0] - dd[2], e1 = dd[1] - dd[3];
    const float S1 = e0 + e1;   // sign over j bits 1..4
    const float SA = e0 - e1;   // sign over all j bits

    const int sb = t | (hq << 14);
    float vals[16];
    #pragma unroll
    for (int w = 0; w < 16; w++) {
        const unsigned r = (w == 0) ? 0x7FFFu : ((0xFFFFu << (15 - w)) & 0xFFFFu);
        float sel;
        if      (w == 1) sel = SP;
        else if (w == 2) sel = S4;
        else if (w == 3) sel = S3;
        else if (w == 4) sel = S2;
        else if (w == 5) sel = S1;
        else             sel = SA;
        vals[w] = (__popc(r & (unsigned)sb) & 1) ? -sel : sel;
    }

    // warp reduction of the 16 partials, then one atomicAdd per value per warp
    #pragma unroll
    for (int w = 0; w < 16; w++) {
        float vv = vals[w];
        #pragma unroll
        for (int o = 16; o > 0; o >>= 1)
            vv += __shfl_xor_sync(0xFFFFFFFFu, vv, o);
        vals[w] = vv;
    }
    const int lane = t & 31;
    if (lane < 16)
        atomicAdd(&out[b * NQ + lane], vals[lane]);
}

__global__ void k_zero(float* __restrict__ out) {
    const int i = blockIdx.x * blockDim.x + threadIdx.x;
    if (i < BATCH * NQ) out[i] = 0.f;
}

extern "C" void kernel_launch(void* const* d_in, const int* in_sizes, int n_in,
                              void* d_out, int out_size) {
    (void)in_sizes; (void)n_in; (void)out_size;
    const float* x      = (const float*)d_in[0];
    const float* params = (const float*)d_in[1];
    float* out = (float*)d_out;

    k_zero<<<(BATCH * NQ + 255) / 256, 256>>>(out);
    k_phase1<<<BATCH * 32, 128>>>(x, params);
    k_phase2<<<BATCH * 4, 512>>>(params, out);
}

// round 2
// speedup vs baseline: 16.7117x; 16.7117x over previous
#include <cuda_runtime.h>

#define NQ 16
#define BATCH 512

// Exact transfer-matrix (MPS, bond dim 2 per branch -> 4 for |psi|^2) evaluation.
//
// Derivation (conventions verified against the round-0 state-vector kernel):
//   v_w = RY(th0_w) RX(x_w) |0> ;  v0=(c0*cx, s0*sx), v1=(s0*cx, -c0*sx)
//   CNOT ring = basis map (Tu)_w = u_0^...^u_w (w>=1), (Tu)_0 = q15 ^ u_0
//   <Z_m> = sum_s (-1)^{parity(r_m & s)} |psi'(s)|^2,
//     r_m = prefix mask {bits 0..m} (m>=1) or {bits 1..15} (m=0)
//   Per-wire s-sum: unsigned -> delta(a,b); signed -> R^T Z R = [[C,-S],[-S,-C]]
//   Bond density f(q,q') updated as f <- D o (B f B^H), B[Q,q] = v[q^Q].
//   Ring wrap handled by 4 boundary terms (P,P'): init uses D0(P^q0, P'^q0'),
//   final contribution is f15(P,P').
__global__ void __launch_bounds__(64) k_expval(const float* __restrict__ x,
                                               const float* __restrict__ params,
                                               float* __restrict__ out) {
    __shared__ float2 v[NQ][2];
    __shared__ float  C1[NQ], S1[NQ];

    const int b   = blockIdx.x;
    const int tid = threadIdx.x;

    if (tid < NQ) {
        const int w = tid;
        float sx, cx; sincosf(0.5f * x[b * NQ + w], &sx, &cx);
        float s0, c0; sincosf(0.5f * params[w],     &s0, &c0);
        v[w][0] = make_float2(c0 * cx,  s0 * sx);
        v[w][1] = make_float2(s0 * cx, -c0 * sx);
        float s1, c1; sincosf(params[NQ + w], &s1, &c1);   // FULL angle for R^T Z R
        C1[w] = c1; S1[w] = s1;
    }
    __syncthreads();

    const int m  = tid >> 2;         // measured wire
    const int P  = tid & 1;          // boundary parity, ket branch
    const int Pp = (tid >> 1) & 1;   // boundary parity, bra branch

    // f[q][q'] complex
    float fr[2][2], fi[2][2];

    // ---- wire 0 init ----
    {
        const bool sgn0 = (m >= 1);          // m==0: wire 0 unsigned
        float D0[2][2];
        if (sgn0) {
            D0[0][0] =  C1[0]; D0[0][1] = -S1[0];
            D0[1][0] = -S1[0]; D0[1][1] = -C1[0];
        } else {
            D0[0][0] = 1.f; D0[0][1] = 0.f;
            D0[1][0] = 0.f; D0[1][1] = 1.f;
        }
        #pragma unroll
        for (int q = 0; q < 2; q++)
            #pragma unroll
            for (int qp = 0; qp < 2; qp++) {
                const float2 a  = v[0][q];
                const float2 bb = v[0][qp];
                // a * conj(bb)
                const float pr = a.x * bb.x + a.y * bb.y;
                const float pi = a.y * bb.x - a.x * bb.y;
                const float d  = D0[P ^ q][Pp ^ qp];
                fr[q][qp] = pr * d;
                fi[q][qp] = pi * d;
            }
    }

    // ---- wires 1..15 ----
    #pragma unroll
    for (int w = 1; w < NQ; w++) {
        const bool sgn = (m >= 1) ? (w <= m) : true;
        const float2 v0 = v[w][0], v1 = v[w][1];

        // g = B f   (B = [[v0,v1],[v1,v0]])
        float gr[2][2], gi[2][2];
        #pragma unroll
        for (int c = 0; c < 2; c++) {
            gr[0][c] = v0.x * fr[0][c] - v0.y * fi[0][c] + v1.x * fr[1][c] - v1.y * fi[1][c];
            gi[0][c] = v0.x * fi[0][c] + v0.y * fr[0][c] + v1.x * fi[1][c] + v1.y * fr[1][c];
            gr[1][c] = v1.x * fr[0][c] - v1.y * fi[0][c] + v0.x * fr[1][c] - v0.y * fi[1][c];
            gi[1][c] = v1.x * fi[0][c] + v1.y * fr[0][c] + v0.x * fi[1][c] + v0.y * fr[1][c];
        }
        // h = g B^H :  h[Q][0] = g[Q][0]*conj(v0) + g[Q][1]*conj(v1)
        //              h[Q][1] = g[Q][0]*conj(v1) + g[Q][1]*conj(v0)
        float hr[2][2], hi[2][2];
        #pragma unroll
        for (int Q = 0; Q < 2; Q++) {
            hr[Q][0] = gr[Q][0] * v0.x + gi[Q][0] * v0.y + gr[Q][1] * v1.x + gi[Q][1] * v1.y;
            hi[Q][0] = gi[Q][0] * v0.x - gr[Q][0] * v0.y + gi[Q][1] * v1.x - gr[Q][1] * v1.y;
            hr[Q][1] = gr[Q][0] * v1.x + gi[Q][0] * v1.y + gr[Q][1] * v0.x + gi[Q][1] * v0.y;
            hi[Q][1] = gi[Q][0] * v1.x - gr[Q][0] * v1.y + gi[Q][1] * v0.x - gr[Q][1] * v0.y;
        }
        // f = D o h
        if (sgn) {
            const float C = C1[w], S = S1[w];
            fr[0][0] =  C * hr[0][0];  fi[0][0] =  C * hi[0][0];
            fr[0][1] = -S * hr[0][1];  fi[0][1] = -S * hi[0][1];
            fr[1][0] = -S * hr[1][0];  fi[1][0] = -S * hi[1][0];
            fr[1][1] = -C * hr[1][1];  fi[1][1] = -C * hi[1][1];
        } else {
            fr[0][0] = hr[0][0];  fi[0][0] = hi[0][0];
            fr[0][1] = 0.f;       fi[0][1] = 0.f;
            fr[1][0] = 0.f;       fi[1][0] = 0.f;
            fr[1][1] = hr[1][1];  fi[1][1] = hi[1][1];
        }
    }

    // contribution of this boundary term: Re f15(P, P')
    float val = P ? (Pp ? fr[1][1] : fr[1][0])
                  : (Pp ? fr[0][1] : fr[0][0]);

    // sum the 4 (P,P') lanes (consecutive lanes share m)
    val += __shfl_xor_sync(0xFFFFFFFFu, val, 1);
    val += __shfl_xor_sync(0xFFFFFFFFu, val, 2);

    if ((tid & 3) == 0)
        out[b * NQ + m] = val;
}

extern "C" void kernel_launch(void* const* d_in, const int* in_sizes, int n_in,
                              void* d_out, int out_size) {
    (void)in_sizes; (void)n_in; (void)out_size;
    const float* x      = (const float*)d_in[0];
    const float* params = (const float*)d_in[1];
    float* out = (float*)d_out;

    k_expval<<<BATCH, 64>>>(x, params, out);
}